// round 3
// baseline (speedup 1.0000x reference)
#include <cuda_runtime.h>
#include <math.h>

// ---------------------------------------------------------------------------
// RotatedIoULoss via Sutherland-Hodgman clipping in box2's local frame.
//
// Box1's corners are rotated into box2's frame, where box2 is the axis-
// aligned rect [-w2/2,w2/2] x [-h2/2,h2/2]. Each clip half-plane test is then
// a single add/sub (s = lim -/+ coord) instead of a cross product. The
// intersection polygon comes out in cyclic order (no atan2, no sort); its
// area is rotation-invariant, so results match the reference construction up
// to fp rounding.
//
// Single kernel: per-block partials + last-block-done final reduction.
// loss = mean( -log(max(inter/(a1+a2-inter), 1e-6)) * weight )
// ---------------------------------------------------------------------------

#define IOU_EPS 1e-6f
#define BLOCK 256
#define MAXB  8192

__device__ float g_partial[MAXB];
__device__ unsigned int g_count = 0;   // reset by last block each launch

__global__ void __launch_bounds__(BLOCK)
rl_main(const float* __restrict__ pred,
        const float* __restrict__ target,
        const float* __restrict__ weight,
        float* __restrict__ out,
        int n, int nb, float inv_n) {
    // ---- coalesced staging of stride-5 rows ----
    __shared__ float sp[BLOCK * 5];
    __shared__ float st[BLOCK * 5];
    int bbase = blockIdx.x * BLOCK;
    int gbase = bbase * 5;
    int limit = n * 5 - gbase;
    for (int j = threadIdx.x; j < BLOCK * 5; j += BLOCK) {
        float vp = 0.f, vt = 0.f;
        if (j < limit) { vp = pred[gbase + j]; vt = target[gbase + j]; }
        sp[j] = vp; st[j] = vt;
    }
    __syncthreads();

    int i = bbase + threadIdx.x;
    float loss = 0.f;
    if (i < n) {
        const float* P = sp + threadIdx.x * 5;
        const float* T = st + threadIdx.x * 5;
        float px = P[0], py = P[1], pw = P[2], ph = P[3], pa = P[4];
        float qx = T[0], qy = T[1], qw = T[2], qh = T[3], qa = T[4];

        // rotate box1 into box2's local frame
        float cb, sb; __sincosf(qa, &sb, &cb);
        float dx = px - qx, dy = py - qy;
        float ox =  dx * cb + dy * sb;     // box1 center in box2 frame
        float oy = -dx * sb + dy * cb;
        float cr, sr; __sincosf(pa - qa, &sr, &cr);  // relative rotation

        float hw = 0.5f * qw, hh = 0.5f * qh;
        float hx = 0.5f * pw, hy = 0.5f * ph;

        // box1 corners (CCW) in box2 frame
        float ax[8], ay[8], bx[8], by[8];
        {
            // corner offsets: (+hx,+hy), (-hx,+hy), (-hx,-hy), (+hx,-hy)
            float ux = hx * cr, uy = hx * sr;     // half-extent along box1-x
            float vxr = -hy * sr, vyr = hy * cr;  // half-extent along box1-y
            ax[0] = ox + ux + vxr; ay[0] = oy + uy + vyr;
            ax[1] = ox - ux + vxr; ay[1] = oy - uy + vyr;
            ax[2] = ox - ux - vxr; ay[2] = oy - uy - vyr;
            ax[3] = ox + ux - vxr; ay[3] = oy + uy - vyr;
        }

        // ---- clip against the 4 axis-aligned half-planes of box2 ----
        float *inx = ax, *iny = ay, *outx = bx, *outy = by;
        int nv = 4;
#pragma unroll
        for (int e = 0; e < 4; e++) {
            // e: 0 -> x<=hw, 1 -> x>=-hw, 2 -> y<=hh, 3 -> y>=-hh
            int axisY = (e >> 1);
            float sgn = (e & 1) ? -1.f : 1.f;
            float lim = axisY ? hh : hw;
            int nv2 = 0;
            float pxk = inx[nv - 1], pyk = iny[nv - 1];
            float sprev = lim - sgn * (axisY ? pyk : pxk);
            for (int k = 0; k < nv; k++) {
                float cx0 = inx[k], cy0 = iny[k];
                float scur = lim - sgn * (axisY ? cy0 : cx0);
                if ((sprev >= 0.f) != (scur >= 0.f)) {
                    float t = __fdividef(sprev, sprev - scur);
                    outx[nv2] = pxk + t * (cx0 - pxk);
                    outy[nv2] = pyk + t * (cy0 - pyk);
                    nv2++;
                }
                if (scur >= 0.f) { outx[nv2] = cx0; outy[nv2] = cy0; nv2++; }
                pxk = cx0; pyk = cy0; sprev = scur;
            }
            nv = nv2;
            float* tmp;
            tmp = inx; inx = outx; outx = tmp;
            tmp = iny; iny = outy; outy = tmp;
            if (nv < 3) { nv = 0; break; }
        }

        // ---- shoelace ----
        float inter = 0.f;
        if (nv >= 3) {
            float s = 0.f;
            float lx = inx[nv - 1], ly = iny[nv - 1];
            for (int k = 0; k < nv; k++) {
                float cx0 = inx[k], cy0 = iny[k];
                s += lx * cy0 - ly * cx0;
                lx = cx0; ly = cy0;
            }
            inter = 0.5f * fabsf(s);
        }

        float a1 = pw * ph, a2 = qw * qh;
        float iou = __fdividef(inter, a1 + a2 - inter);
        iou = fmaxf(iou, IOU_EPS);
        loss = -__logf(iou) * weight[i];
    }

    // ---- block reduction -> per-block partial ----
    unsigned mask = 0xFFFFFFFFu;
#pragma unroll
    for (int o = 16; o > 0; o >>= 1)
        loss += __shfl_down_sync(mask, loss, o);

    __shared__ float ws[BLOCK / 32];
    int lane = threadIdx.x & 31;
    int wid = threadIdx.x >> 5;
    if (lane == 0) ws[wid] = loss;
    __syncthreads();
    __shared__ bool is_last;
    if (threadIdx.x == 0) {
        float v = 0.f;
#pragma unroll
        for (int w = 0; w < BLOCK / 32; w++) v += ws[w];
        g_partial[blockIdx.x] = v;
        __threadfence();
        unsigned prev = atomicAdd(&g_count, 1u);
        is_last = (prev == (unsigned)(nb - 1));
    }
    __syncthreads();

    // ---- last block: final reduction over all partials (deterministic) ----
    if (is_last) {
        double s = 0.0;
        for (int j = threadIdx.x; j < nb; j += BLOCK)
            s += (double)g_partial[j];
#pragma unroll
        for (int o = 16; o > 0; o >>= 1)
            s += __shfl_down_sync(mask, s, o);
        __shared__ double ds[BLOCK / 32];
        if (lane == 0) ds[wid] = s;
        __syncthreads();
        if (threadIdx.x == 0) {
            double v = 0.0;
#pragma unroll
            for (int w = 0; w < BLOCK / 32; w++) v += ds[w];
            out[0] = (float)(v * (double)inv_n);
            g_count = 0;  // reset for next graph replay
        }
    }
}

extern "C" void kernel_launch(void* const* d_in, const int* in_sizes, int n_in,
                              void* d_out, int out_size) {
    const float* pred   = (const float*)d_in[0];
    const float* target = (const float*)d_in[1];
    const float* weight = (const float*)d_in[2];
    float* out = (float*)d_out;
    int n = in_sizes[2];

    int grid = (n + BLOCK - 1) / BLOCK;
    if (grid > MAXB) grid = MAXB;  // n = 1e6 -> 3907 blocks; guard only
    rl_main<<<grid, BLOCK>>>(pred, target, weight, out, n, grid,
                             1.0f / (float)n);
}

// round 4
// speedup vs baseline: 1.7715x; 1.7715x over previous
#include <cuda_runtime.h>
#include <math.h>

// ---------------------------------------------------------------------------
// RotatedIoULoss — branch-free slab clipping, fully register-resident.
//
// Box1 is rotated into box2's frame (box2 becomes the axis-aligned slab pair
// [-hw,hw] x [-hh,hh]). Clip stage 1 (x-slab): each of the 4 edges statically
// emits 3 points: [first crossing | dup], [second crossing | dup], clamped
// endpoint. Duplicate points and excursions along a clip line contribute zero
// net shoelace area, so the 12-point sequence encloses exactly area(box1 ∩
// x-slab). Stage 2 does the same against the y-slab over the 12 edges,
// accumulating shoelace terms on the fly. No dynamic indexing -> everything
// stays in registers; no data-dependent loops -> no divergence.
//
// loss = mean( -log(max(inter/(a1+a2-inter), 1e-6)) * weight )
// ---------------------------------------------------------------------------

#define IOU_EPS 1e-6f
#define BLOCK 256
#define MAXB  8192

__device__ float g_partial[MAXB];
__device__ unsigned int g_count = 0;   // reset by last block each launch

__global__ void __launch_bounds__(BLOCK)
rl_main(const float* __restrict__ pred,
        const float* __restrict__ target,
        const float* __restrict__ weight,
        float* __restrict__ out,
        int n, int nb, float inv_n) {
    // ---- coalesced staging of stride-5 rows ----
    __shared__ float sp[BLOCK * 5];
    __shared__ float st[BLOCK * 5];
    int bbase = blockIdx.x * BLOCK;
    int gbase = bbase * 5;
    int limit = n * 5 - gbase;
    for (int j = threadIdx.x; j < BLOCK * 5; j += BLOCK) {
        float vp = 0.f, vt = 0.f;
        if (j < limit) { vp = pred[gbase + j]; vt = target[gbase + j]; }
        sp[j] = vp; st[j] = vt;
    }
    __syncthreads();

    int i = bbase + threadIdx.x;
    float loss = 0.f;
    if (i < n) {
        const float* P = sp + threadIdx.x * 5;
        const float* T = st + threadIdx.x * 5;
        float px = P[0], py = P[1], pw = P[2], ph = P[3], pa = P[4];
        float qx = T[0], qy = T[1], qw = T[2], qh = T[3], qa = T[4];

        // box1 in box2's local frame
        float cb, sb; __sincosf(qa, &sb, &cb);
        float dxc = px - qx, dyc = py - qy;
        float ox =  dxc * cb + dyc * sb;
        float oy = -dxc * sb + dyc * cb;
        float cr, sr; __sincosf(pa - qa, &sr, &cr);

        float hw = 0.5f * qw, hh = 0.5f * qh;
        float hx = 0.5f * pw, hy = 0.5f * ph;

        float ux = hx * cr,  uy = hx * sr;
        float wx_ = -hy * sr, wy_ = hy * cr;
        float vx[4], vy[4];
        vx[0] = ox + ux + wx_; vy[0] = oy + uy + wy_;
        vx[1] = ox - ux + wx_; vy[1] = oy - uy + wy_;
        vx[2] = ox - ux - wx_; vy[2] = oy - uy - wy_;
        vx[3] = ox + ux - wx_; vy[3] = oy + uy - wy_;

        // ---- stage 1: clip to x in [-hw, hw]; emit 12 points (static) ----
        float ex[12], ey[12];
#pragma unroll
        for (int k = 0; k < 4; k++) {
            float x0 = vx[(k + 3) & 3], y0 = vy[(k + 3) & 3];
            float x1 = vx[k], y1 = vy[k];
            float dxe = x1 - x0, dye = y1 - y0;
            float inv = __fdividef(1.f, dxe);
            float yA = fmaf((-hw - x0) * inv, dye, y0);  // crossing x=-hw
            float yB = fmaf(( hw - x0) * inv, dye, y0);  // crossing x=+hw
            bool crossA = (x0 < -hw) != (x1 < -hw);
            bool crossB = (x0 >  hw) != (x1 >  hw);
            bool rightd = dxe > 0.f;
            bool has1 = crossA || crossB;
            bool has2 = crossA && crossB;
            bool firstIsA = rightd ? crossA : !crossB;
            float X1x = firstIsA ? -hw : hw;
            float X1y = firstIsA ? yA  : yB;
            float X2x = rightd ? hw : -hw;
            float X2y = rightd ? yB : yA;
            float ccx = fminf(fmaxf(x1, -hw), hw);
            float ccy = y1;
            ex[3*k+0] = has1 ? X1x : ccx;  ey[3*k+0] = has1 ? X1y : ccy;
            ex[3*k+1] = has2 ? X2x : ccx;  ey[3*k+1] = has2 ? X2y : ccy;
            ex[3*k+2] = ccx;               ey[3*k+2] = ccy;
        }

        // ---- stage 2: clip to y in [-hh, hh], fold into shoelace ----
        float s = 0.f;
        float lx = ex[11];
        float ly = fminf(fmaxf(ey[11], -hh), hh);
        float x0 = ex[11], y0 = ey[11];
#pragma unroll
        for (int k = 0; k < 12; k++) {
            float x1 = ex[k], y1 = ey[k];
            float dxe = x1 - x0, dye = y1 - y0;
            float inv = __fdividef(1.f, dye);
            float xA = fmaf((-hh - y0) * inv, dxe, x0);  // crossing y=-hh
            float xB = fmaf(( hh - y0) * inv, dxe, x0);  // crossing y=+hh
            bool crossA = (y0 < -hh) != (y1 < -hh);
            bool crossB = (y0 >  hh) != (y1 >  hh);
            bool upd = dye > 0.f;
            bool has1 = crossA || crossB;
            bool has2 = crossA && crossB;
            bool firstIsA = upd ? crossA : !crossB;
            float X1y = firstIsA ? -hh : hh;
            float X1x = firstIsA ? xA  : xB;
            float X2y = upd ? hh : -hh;
            float X2x = upd ? xB : xA;
            float ccy = fminf(fmaxf(y1, -hh), hh);
            float ccx = x1;
            float p1x = has1 ? X1x : ccx, p1y = has1 ? X1y : ccy;
            float p2x = has2 ? X2x : ccx, p2y = has2 ? X2y : ccy;
            s += lx * p1y - ly * p1x;  lx = p1x; ly = p1y;
            s += lx * p2y - ly * p2x;  lx = p2x; ly = p2y;
            s += lx * ccy - ly * ccx;  lx = ccx; ly = ccy;
            x0 = x1; y0 = y1;
        }
        float inter = 0.5f * fabsf(s);

        // conservative separation test: certain-disjoint -> exact zero
        // (projection of box1 onto any axis <= hx + hy)
        float rad = hx + hy;
        if (fabsf(ox) > hw + rad || fabsf(oy) > hh + rad) inter = 0.f;

        float a1 = pw * ph, a2 = qw * qh;
        float iou = __fdividef(inter, a1 + a2 - inter);
        iou = fmaxf(iou, IOU_EPS);
        loss = -__logf(iou) * weight[i];
    }

    // ---- block reduction -> per-block partial ----
    unsigned mask = 0xFFFFFFFFu;
#pragma unroll
    for (int o = 16; o > 0; o >>= 1)
        loss += __shfl_down_sync(mask, loss, o);

    __shared__ float ws[BLOCK / 32];
    int lane = threadIdx.x & 31;
    int wid = threadIdx.x >> 5;
    if (lane == 0) ws[wid] = loss;
    __syncthreads();
    __shared__ bool is_last;
    if (threadIdx.x == 0) {
        float v = 0.f;
#pragma unroll
        for (int w = 0; w < BLOCK / 32; w++) v += ws[w];
        g_partial[blockIdx.x] = v;
        __threadfence();
        unsigned prev = atomicAdd(&g_count, 1u);
        is_last = (prev == (unsigned)(nb - 1));
    }
    __syncthreads();

    // ---- last block: final reduction over all partials (deterministic) ----
    if (is_last) {
        double s = 0.0;
        for (int j = threadIdx.x; j < nb; j += BLOCK)
            s += (double)g_partial[j];
#pragma unroll
        for (int o = 16; o > 0; o >>= 1)
            s += __shfl_down_sync(mask, s, o);
        __shared__ double ds[BLOCK / 32];
        if (lane == 0) ds[wid] = s;
        __syncthreads();
        if (threadIdx.x == 0) {
            double v = 0.0;
#pragma unroll
            for (int w = 0; w < BLOCK / 32; w++) v += ds[w];
            out[0] = (float)(v * (double)inv_n);
            g_count = 0;  // reset for next graph replay
        }
    }
}

extern "C" void kernel_launch(void* const* d_in, const int* in_sizes, int n_in,
                              void* d_out, int out_size) {
    const float* pred   = (const float*)d_in[0];
    const float* target = (const float*)d_in[1];
    const float* weight = (const float*)d_in[2];
    float* out = (float*)d_out;
    int n = in_sizes[2];

    int grid = (n + BLOCK - 1) / BLOCK;
    if (grid > MAXB) grid = MAXB;  // n = 1e6 -> 3907 blocks
    rl_main<<<grid, BLOCK>>>(pred, target, weight, out, n, grid,
                             1.0f / (float)n);
}

// round 5
// speedup vs baseline: 2.0924x; 1.1812x over previous
#include <cuda_runtime.h>
#include <math.h>

// ---------------------------------------------------------------------------
// RotatedIoULoss — fused t-clamp slab clipping, boolean-free, register-only.
//
// Box1 in box2's frame; box2 = slab pair [-hw,hw] x [-hh,hh].
// For each polygon edge clipped to a slab, emit 3 points via the parametric
// clamp identity: te=clamp01(t_entry), tx=clamp01(t_exit) ->
// (P(te), P(tx), clamped endpoint). Inside edges, outside edges, and
// boundary-degenerate cases (0*inf NaN under fmin/fmax) all reduce to
// duplicate points / boundary excursions with zero net shoelace area.
// Stage 1 (x-slab) points are consumed immediately by stage 2 (y-slab),
// which folds directly into two alternating shoelace accumulators.
// ---------------------------------------------------------------------------

#define IOU_EPS 1e-6f
#define BLOCK 256
#define MAXB  8192

__device__ float g_partial[MAXB];
__device__ unsigned int g_count = 0;   // reset by last block each launch

__device__ __forceinline__ float clamp01(float t) {
    return fminf(fmaxf(t, 0.f), 1.f);
}

__global__ void __launch_bounds__(BLOCK, 5)
rl_main(const float* __restrict__ pred,
        const float* __restrict__ target,
        const float* __restrict__ weight,
        float* __restrict__ out,
        int n, int nb, float inv_n) {
    // ---- coalesced staging of stride-5 rows ----
    __shared__ float sp[BLOCK * 5];
    __shared__ float st[BLOCK * 5];
    int bbase = blockIdx.x * BLOCK;
    int gbase = bbase * 5;
    int limit = n * 5 - gbase;
    for (int j = threadIdx.x; j < BLOCK * 5; j += BLOCK) {
        float vp = 0.f, vt = 0.f;
        if (j < limit) { vp = pred[gbase + j]; vt = target[gbase + j]; }
        sp[j] = vp; st[j] = vt;
    }
    __syncthreads();

    int i = bbase + threadIdx.x;
    float loss = 0.f;
    if (i < n) {
        const float* P = sp + threadIdx.x * 5;
        const float* T = st + threadIdx.x * 5;
        float px = P[0], py = P[1], pw = P[2], ph = P[3], pa = P[4];
        float qx = T[0], qy = T[1], qw = T[2], qh = T[3], qa = T[4];

        // box1 in box2's local frame
        float cb, sb; __sincosf(qa, &sb, &cb);
        float dxc = px - qx, dyc = py - qy;
        float ox =  dxc * cb + dyc * sb;
        float oy = -dxc * sb + dyc * cb;
        float cr, sr; __sincosf(pa - qa, &sr, &cr);

        float hw = 0.5f * qw, hh = 0.5f * qh;
        float hx = 0.5f * pw, hy = 0.5f * ph;

        float ux = hx * cr,  uy = hx * sr;
        float wx_ = -hy * sr, wy_ = hy * cr;
        // rectangle corners (CCW)
        float vx0 = ox + ux + wx_, vy0 = oy + uy + wy_;
        float vx1 = ox - ux + wx_, vy1 = oy - uy + wy_;
        float vx2 = ox - ux - wx_, vy2 = oy - uy - wy_;
        float vx3 = ox + ux - wx_, vy3 = oy + uy - wy_;

        // stage-2 state: previous unclipped point + previous clipped point
        float x0s = fminf(fmaxf(vx3, -hw), hw);  // last stage-1 output point
        float y0s = vy3;
        float lx = x0s, ly = fminf(fmaxf(y0s, -hh), hh);
        float s0 = 0.f, s1 = 0.f;

        // stage-2 step: edge (x0s,y0s)->(nx,ny) clipped to y-slab -> shoelace
#define STEP(nx, ny) do {                                              \
            float dyE = (ny) - y0s, dxE = (nx) - x0s;                  \
            float inv = __fdividef(1.f, dyE);                          \
            float tlo = (-hh - y0s) * inv;                             \
            float thi = ( hh - y0s) * inv;                             \
            float tin  = (dyE > 0.f) ? tlo : thi;                      \
            float tout = (dyE > 0.f) ? thi : tlo;                      \
            float te = clamp01(tin);                                   \
            float tx = clamp01(tout);                                  \
            float p1x = fmaf(te, dxE, x0s);                            \
            float p1y = fminf(fmaxf(fmaf(te, dyE, y0s), -hh), hh);     \
            float p2x = fmaf(tx, dxE, x0s);                            \
            float p2y = fminf(fmaxf(fmaf(tx, dyE, y0s), -hh), hh);     \
            float p3x = (nx);                                          \
            float p3y = fminf(fmaxf((ny), -hh), hh);                   \
            s0 += lx * p1y - ly * p1x;                                 \
            s1 += p1x * p2y - p1y * p2x;                               \
            s0 += p2x * p3y - p2y * p3x;                               \
            lx = p3x; ly = p3y;                                        \
            x0s = (nx); y0s = (ny);                                    \
        } while (0)

        // stage-1 edge: (ax,ay)->(bx,by) clipped to x-slab, emit 3 pts
#define EDGE(axv, ayv, bxv, byv) do {                                  \
            float dxE = (bxv) - (axv), dyE = (byv) - (ayv);            \
            float inv = __fdividef(1.f, dxE);                          \
            float tlo = (-hw - (axv)) * inv;                           \
            float thi = ( hw - (axv)) * inv;                           \
            float tin  = (dxE > 0.f) ? tlo : thi;                      \
            float tout = (dxE > 0.f) ? thi : tlo;                      \
            float te = clamp01(tin);                                   \
            float tx = clamp01(tout);                                  \
            float e1x = fminf(fmaxf(fmaf(te, dxE, (axv)), -hw), hw);   \
            float e1y = fmaf(te, dyE, (ayv));                          \
            float e2x = fminf(fmaxf(fmaf(tx, dxE, (axv)), -hw), hw);   \
            float e2y = fmaf(tx, dyE, (ayv));                          \
            float e3x = fminf(fmaxf((bxv), -hw), hw);                  \
            float e3y = (byv);                                         \
            STEP(e1x, e1y);                                            \
            STEP(e2x, e2y);                                            \
            STEP(e3x, e3y);                                            \
        } while (0)

        EDGE(vx3, vy3, vx0, vy0);
        EDGE(vx0, vy0, vx1, vy1);
        EDGE(vx1, vy1, vx2, vy2);
        EDGE(vx2, vy2, vx3, vy3);
#undef EDGE
#undef STEP

        float inter = 0.5f * fabsf(s0 + s1);

        // conservative separation: certain-disjoint -> exact zero
        float rad = hx + hy;
        if (fabsf(ox) > hw + rad || fabsf(oy) > hh + rad) inter = 0.f;

        float a1 = pw * ph, a2 = qw * qh;
        float iou = __fdividef(inter, a1 + a2 - inter);
        iou = fmaxf(iou, IOU_EPS);
        loss = -__logf(iou) * weight[i];
    }

    // ---- block reduction -> per-block partial ----
    unsigned mask = 0xFFFFFFFFu;
#pragma unroll
    for (int o = 16; o > 0; o >>= 1)
        loss += __shfl_down_sync(mask, loss, o);

    __shared__ float ws[BLOCK / 32];
    int lane = threadIdx.x & 31;
    int wid = threadIdx.x >> 5;
    if (lane == 0) ws[wid] = loss;
    __syncthreads();
    __shared__ bool is_last;
    if (threadIdx.x == 0) {
        float v = 0.f;
#pragma unroll
        for (int w = 0; w < BLOCK / 32; w++) v += ws[w];
        g_partial[blockIdx.x] = v;
        __threadfence();
        unsigned prev = atomicAdd(&g_count, 1u);
        is_last = (prev == (unsigned)(nb - 1));
    }
    __syncthreads();

    // ---- last block: final reduction (deterministic) ----
    if (is_last) {
        double s = 0.0;
        for (int j = threadIdx.x; j < nb; j += BLOCK)
            s += (double)g_partial[j];
#pragma unroll
        for (int o = 16; o > 0; o >>= 1)
            s += __shfl_down_sync(mask, s, o);
        __shared__ double ds[BLOCK / 32];
        if (lane == 0) ds[wid] = s;
        __syncthreads();
        if (threadIdx.x == 0) {
            double v = 0.0;
#pragma unroll
            for (int w = 0; w < BLOCK / 32; w++) v += ds[w];
            out[0] = (float)(v * (double)inv_n);
            g_count = 0;  // reset for next graph replay
        }
    }
}

extern "C" void kernel_launch(void* const* d_in, const int* in_sizes, int n_in,
                              void* d_out, int out_size) {
    const float* pred   = (const float*)d_in[0];
    const float* target = (const float*)d_in[1];
    const float* weight = (const float*)d_in[2];
    float* out = (float*)d_out;
    int n = in_sizes[2];

    int grid = (n + BLOCK - 1) / BLOCK;
    if (grid > MAXB) grid = MAXB;  // n = 1e6 -> 3907 blocks
    rl_main<<<grid, BLOCK>>>(pred, target, weight, out, n, grid,
                             1.0f / (float)n);
}

// round 6
// speedup vs baseline: 2.3644x; 1.1300x over previous
#include <cuda_runtime.h>
#include <math.h>

// ---------------------------------------------------------------------------
// RotatedIoULoss — exact clamped-image shoelace (Green's theorem form).
//
// Box1 in box2's frame; box2 = [-hw,hw] x [-hh,hh].
// area(P ∩ box) = signed area enclosed by Φ(∂P), Φ(x,y)=(clampx, clampy):
// by Green's theorem ∮ F dG with F=clamp(x), G=clamp(y) integrates the
// indicator of the box over P (the straight-line homotopy id→Φ never enters
// the box interior, so winding numbers inside the box are preserved).
// Φ of an edge is piecewise-affine; breakpoints are the crossings with the
// 4 clip lines. Per edge: 2 divides -> 4 crossing t's -> clamp01 -> merge of
// two sorted pairs -> 4 interior points + clamped corner -> 5 shoelace pts.
// 20 points, 8 divides total, no booleans (min/max only). Degenerate edges
// produce NaN/inf t's that clamp to duplicate points (zero net area).
// ---------------------------------------------------------------------------

#define IOU_EPS 1e-6f
#define BLOCK 256
#define MAXB  8192

__device__ float g_partial[MAXB];
__device__ unsigned int g_count = 0;   // reset by last block each launch

__device__ __forceinline__ float clamp01(float t) {
    return fminf(fmaxf(t, 0.f), 1.f);
}
__device__ __forceinline__ float clampab(float v, float h) {
    return fminf(fmaxf(v, -h), h);
}

__global__ void __launch_bounds__(BLOCK, 5)
rl_main(const float* __restrict__ pred,
        const float* __restrict__ target,
        const float* __restrict__ weight,
        float* __restrict__ out,
        int n, int nb, float inv_n) {
    // ---- coalesced staging of stride-5 rows ----
    __shared__ float sp[BLOCK * 5];
    __shared__ float st[BLOCK * 5];
    int bbase = blockIdx.x * BLOCK;
    int gbase = bbase * 5;
    int limit = n * 5 - gbase;
    for (int j = threadIdx.x; j < BLOCK * 5; j += BLOCK) {
        float vp = 0.f, vt = 0.f;
        if (j < limit) { vp = pred[gbase + j]; vt = target[gbase + j]; }
        sp[j] = vp; st[j] = vt;
    }
    __syncthreads();

    int i = bbase + threadIdx.x;
    float loss = 0.f;
    if (i < n) {
        const float* P = sp + threadIdx.x * 5;
        const float* T = st + threadIdx.x * 5;
        float px = P[0], py = P[1], pw = P[2], ph = P[3], pa = P[4];
        float qx = T[0], qy = T[1], qw = T[2], qh = T[3], qa = T[4];

        // box1 in box2's local frame
        float cb, sb; __sincosf(qa, &sb, &cb);
        float dxc = px - qx, dyc = py - qy;
        float ox =  dxc * cb + dyc * sb;
        float oy = -dxc * sb + dyc * cb;
        float cr, sr; __sincosf(pa - qa, &sr, &cr);

        float hw = 0.5f * qw, hh = 0.5f * qh;
        float hx = 0.5f * pw, hy = 0.5f * ph;

        float ux = hx * cr,  uy = hx * sr;
        float wxr = -hy * sr, wyr = hy * cr;
        // rectangle corners (CCW) and their clamped images
        float vx[4], vy[4], cx[4], cy[4];
        vx[0] = ox + ux + wxr; vy[0] = oy + uy + wyr;
        vx[1] = ox - ux + wxr; vy[1] = oy - uy + wyr;
        vx[2] = ox - ux - wxr; vy[2] = oy - uy - wyr;
        vx[3] = ox + ux - wxr; vy[3] = oy + uy - wyr;
#pragma unroll
        for (int k = 0; k < 4; k++) {
            cx[k] = clampab(vx[k], hw);
            cy[k] = clampab(vy[k], hh);
        }

        float lx = cx[3], ly = cy[3];   // previous clamped path point
        float s0 = 0.f, s1 = 0.f;

#pragma unroll
        for (int k = 0; k < 4; k++) {
            int kp = (k + 3) & 3;           // edge: corner kp -> corner k
            float axv = vx[kp], ayv = vy[kp];
            float dxe = vx[k] - axv, dye = vy[k] - ayv;
            float invx = __fdividef(1.f, dxe);
            float invy = __fdividef(1.f, dye);
            float ta = (-hw - axv) * invx, tb = (hw - axv) * invx;
            float tc = (-hh - ayv) * invy, td = (hh - ayv) * invy;
            float tx1 = clamp01(fminf(ta, tb)), tx2 = clamp01(fmaxf(ta, tb));
            float ty1 = clamp01(fminf(tc, td)), ty2 = clamp01(fmaxf(tc, td));
            // merge two sorted pairs -> s1..s4
            float m1 = fminf(tx1, ty1);
            float m4 = fmaxf(tx2, ty2);
            float u  = fmaxf(tx1, ty1);
            float v  = fminf(tx2, ty2);
            float m2 = fminf(u, v);
            float m3 = fmaxf(u, v);

            float p1x = clampab(fmaf(m1, dxe, axv), hw);
            float p1y = clampab(fmaf(m1, dye, ayv), hh);
            float p2x = clampab(fmaf(m2, dxe, axv), hw);
            float p2y = clampab(fmaf(m2, dye, ayv), hh);
            float p3x = clampab(fmaf(m3, dxe, axv), hw);
            float p3y = clampab(fmaf(m3, dye, ayv), hh);
            float p4x = clampab(fmaf(m4, dxe, axv), hw);
            float p4y = clampab(fmaf(m4, dye, ayv), hh);
            float p5x = cx[k], p5y = cy[k];

            s0 += lx  * p1y - ly  * p1x;
            s1 += p1x * p2y - p1y * p2x;
            s0 += p2x * p3y - p2y * p3x;
            s1 += p3x * p4y - p3y * p4x;
            s0 += p4x * p5y - p4y * p5x;
            lx = p5x; ly = p5y;
        }

        float inter = 0.5f * fabsf(s0 + s1);

        // conservative separation: certain-disjoint -> exact zero
        float rad = hx + hy;
        if (fabsf(ox) > hw + rad || fabsf(oy) > hh + rad) inter = 0.f;

        float a1 = pw * ph, a2 = qw * qh;
        float iou = __fdividef(inter, a1 + a2 - inter);
        iou = fmaxf(iou, IOU_EPS);
        loss = -__logf(iou) * weight[i];
    }

    // ---- block reduction -> per-block partial ----
    unsigned mask = 0xFFFFFFFFu;
#pragma unroll
    for (int o = 16; o > 0; o >>= 1)
        loss += __shfl_down_sync(mask, loss, o);

    __shared__ float ws[BLOCK / 32];
    int lane = threadIdx.x & 31;
    int wid = threadIdx.x >> 5;
    if (lane == 0) ws[wid] = loss;
    __syncthreads();
    __shared__ bool is_last;
    if (threadIdx.x == 0) {
        float v = 0.f;
#pragma unroll
        for (int w = 0; w < BLOCK / 32; w++) v += ws[w];
        g_partial[blockIdx.x] = v;
        __threadfence();
        unsigned prev = atomicAdd(&g_count, 1u);
        is_last = (prev == (unsigned)(nb - 1));
    }
    __syncthreads();

    // ---- last block: final reduction (deterministic) ----
    if (is_last) {
        double s = 0.0;
        for (int j = threadIdx.x; j < nb; j += BLOCK)
            s += (double)g_partial[j];
#pragma unroll
        for (int o = 16; o > 0; o >>= 1)
            s += __shfl_down_sync(mask, s, o);
        __shared__ double ds[BLOCK / 32];
        if (lane == 0) ds[wid] = s;
        __syncthreads();
        if (threadIdx.x == 0) {
            double v = 0.0;
#pragma unroll
            for (int w = 0; w < BLOCK / 32; w++) v += ds[w];
            out[0] = (float)(v * (double)inv_n);
            g_count = 0;  // reset for next graph replay
        }
    }
}

extern "C" void kernel_launch(void* const* d_in, const int* in_sizes, int n_in,
                              void* d_out, int out_size) {
    const float* pred   = (const float*)d_in[0];
    const float* target = (const float*)d_in[1];
    const float* weight = (const float*)d_in[2];
    float* out = (float*)d_out;
    int n = in_sizes[2];

    int grid = (n + BLOCK - 1) / BLOCK;
    if (grid > MAXB) grid = MAXB;  // n = 1e6 -> 3907 blocks
    rl_main<<<grid, BLOCK>>>(pred, target, weight, out, n, grid,
                             1.0f / (float)n);
}

// round 7
// speedup vs baseline: 2.9464x; 1.2462x over previous
#include <cuda_runtime.h>
#include <math.h>

// ---------------------------------------------------------------------------
// RotatedIoULoss — exact clamped-image shoelace (Green's theorem form).
//
// Box1 in box2's frame; box2 = [-hw,hw] x [-hh,hh].
// area(P ∩ box) = signed area enclosed by Φ(∂P), Φ(x,y)=(clampx, clampy).
// Φ of an edge is piecewise-affine; breakpoints are the crossings with the
// 4 clip lines: per edge 2 rcp -> 4 crossing t's (FMA form) -> merge ->
// clamp01 -> 4 interior points + clamped corner -> 5 shoelace points.
// Degenerate edges produce NaN/inf t's that collapse to duplicate points
// (zero net area) under CUDA fminf/fmaxf NaN semantics.
// ---------------------------------------------------------------------------

#define IOU_EPS 1e-6f
#define BLOCK 256
#define MAXB  8192

__device__ float g_partial[MAXB];
__device__ unsigned int g_count = 0;   // reset by last block each launch

__device__ __forceinline__ float clamp01(float t) {
    return fminf(fmaxf(t, 0.f), 1.f);
}
__device__ __forceinline__ float clampab(float v, float h) {
    return fminf(fmaxf(v, -h), h);
}

__global__ void __launch_bounds__(BLOCK, 6)
rl_main(const float* __restrict__ pred,
        const float* __restrict__ target,
        const float* __restrict__ weight,
        float* __restrict__ out,
        int n, int nb, float inv_n) {
    // ---- coalesced float4 staging of stride-5 rows ----
    __shared__ float4 sp4[BLOCK * 5 / 4];
    __shared__ float4 st4[BLOCK * 5 / 4];
    float* sp = (float*)sp4;
    float* st = (float*)st4;
    int bbase = blockIdx.x * BLOCK;
    int gbase = bbase * 5;                 // 16B-aligned (BLOCK*5*4 % 16 == 0)
    int limit = n * 5 - gbase;             // valid floats in this block's span
    const float4* p4 = (const float4*)(pred + gbase);
    const float4* t4 = (const float4*)(target + gbase);
    for (int j = threadIdx.x; j < BLOCK * 5 / 4; j += BLOCK) {
        float4 vp = make_float4(0.f, 0.f, 0.f, 0.f);
        float4 vt = vp;
        int e0 = j * 4;
        if (e0 + 3 < limit) {
            vp = p4[j]; vt = t4[j];
        } else if (e0 < limit) {           // rare boundary thread
            const float* ps = pred + gbase;
            const float* ts = target + gbase;
            float* vpf = &vp.x; float* vtf = &vt.x;
            for (int c = 0; c < 4; c++)
                if (e0 + c < limit) { vpf[c] = ps[e0 + c]; vtf[c] = ts[e0 + c]; }
        }
        sp4[j] = vp; st4[j] = vt;
    }
    __syncthreads();

    int i = bbase + threadIdx.x;
    float loss = 0.f;
    if (i < n) {
        float w = weight[i];
        const float* P = sp + threadIdx.x * 5;
        const float* T = st + threadIdx.x * 5;
        float px = P[0], py = P[1], pw = P[2], ph = P[3], pa = P[4];
        float qx = T[0], qy = T[1], qw = T[2], qh = T[3], qa = T[4];

        // box1 in box2's local frame
        float cb, sb; __sincosf(qa, &sb, &cb);
        float dxc = px - qx, dyc = py - qy;
        float ox =  dxc * cb + dyc * sb;
        float oy = -dxc * sb + dyc * cb;
        float cr, sr; __sincosf(pa - qa, &sr, &cr);

        float hw = 0.5f * qw, hh = 0.5f * qh;
        float hx = 0.5f * pw, hy = 0.5f * ph;

        float ux = hx * cr,  uy = hx * sr;
        float wxr = -hy * sr, wyr = hy * cr;
        // rectangle corners (CCW)
        float vx0 = ox + ux + wxr, vy0 = oy + uy + wyr;
        float vx1 = ox - ux + wxr, vy1 = oy - uy + wyr;
        float vx2 = ox - ux - wxr, vy2 = oy - uy - wyr;
        float vx3 = ox + ux - wxr, vy3 = oy + uy - wyr;

        float lx = clampab(vx3, hw), ly = clampab(vy3, hh);
        float s0 = 0.f, s1 = 0.f, s2 = 0.f, s3 = 0.f;

#define EDGE(axv, ayv, bxv, byv) do {                                   \
            float dxe = (bxv) - (axv), dye = (byv) - (ayv);             \
            float invx = __fdividef(1.f, dxe);                          \
            float invy = __fdividef(1.f, dye);                          \
            float hwi = hw * invx, hhi = hh * invy;                     \
            float ta = fmaf((axv), -invx, -hwi);                        \
            float tb = fmaf((axv), -invx,  hwi);                        \
            float tc = fmaf((ayv), -invy, -hhi);                        \
            float td = fmaf((ayv), -invy,  hhi);                        \
            float tx1 = fminf(ta, tb), tx2 = fmaxf(ta, tb);             \
            float ty1 = fminf(tc, td), ty2 = fmaxf(tc, td);             \
            float m1 = clamp01(fminf(tx1, ty1));                        \
            float m4 = clamp01(fmaxf(tx2, ty2));                        \
            float uu = fmaxf(tx1, ty1), vv = fminf(tx2, ty2);           \
            float m2 = clamp01(fminf(uu, vv));                          \
            float m3 = clamp01(fmaxf(uu, vv));                          \
            float p1x = clampab(fmaf(m1, dxe, (axv)), hw);              \
            float p1y = clampab(fmaf(m1, dye, (ayv)), hh);              \
            float p2x = clampab(fmaf(m2, dxe, (axv)), hw);              \
            float p2y = clampab(fmaf(m2, dye, (ayv)), hh);              \
            float p3x = clampab(fmaf(m3, dxe, (axv)), hw);              \
            float p3y = clampab(fmaf(m3, dye, (ayv)), hh);              \
            float p4x = clampab(fmaf(m4, dxe, (axv)), hw);              \
            float p4y = clampab(fmaf(m4, dye, (ayv)), hh);              \
            float p5x = clampab((bxv), hw);                             \
            float p5y = clampab((byv), hh);                             \
            s0 = fmaf(lx,  p1y, s0); s0 = fmaf(-ly,  p1x, s0);          \
            s1 = fmaf(p1x, p2y, s1); s1 = fmaf(-p1y, p2x, s1);          \
            s2 = fmaf(p2x, p3y, s2); s2 = fmaf(-p2y, p3x, s2);          \
            s3 = fmaf(p3x, p4y, s3); s3 = fmaf(-p3y, p4x, s3);          \
            s0 = fmaf(p4x, p5y, s0); s0 = fmaf(-p4y, p5x, s0);          \
            lx = p5x; ly = p5y;                                         \
        } while (0)

        EDGE(vx3, vy3, vx0, vy0);
        EDGE(vx0, vy0, vx1, vy1);
        EDGE(vx1, vy1, vx2, vy2);
        EDGE(vx2, vy2, vx3, vy3);
#undef EDGE

        float inter = 0.5f * fabsf((s0 + s1) + (s2 + s3));

        // conservative separation: certain-disjoint -> exact zero
        float rad = hx + hy;
        if (fabsf(ox) > hw + rad || fabsf(oy) > hh + rad) inter = 0.f;

        float a1 = pw * ph, a2 = qw * qh;
        float iou = __fdividef(inter, a1 + a2 - inter);
        iou = fmaxf(iou, IOU_EPS);
        loss = -__logf(iou) * w;
    }

    // ---- block reduction -> per-block partial ----
    unsigned mask = 0xFFFFFFFFu;
#pragma unroll
    for (int o = 16; o > 0; o >>= 1)
        loss += __shfl_down_sync(mask, loss, o);

    __shared__ float ws[BLOCK / 32];
    int lane = threadIdx.x & 31;
    int wid = threadIdx.x >> 5;
    if (lane == 0) ws[wid] = loss;
    __syncthreads();
    __shared__ bool is_last;
    if (threadIdx.x == 0) {
        float v = 0.f;
#pragma unroll
        for (int w = 0; w < BLOCK / 32; w++) v += ws[w];
        g_partial[blockIdx.x] = v;
        __threadfence();
        unsigned prev = atomicAdd(&g_count, 1u);
        is_last = (prev == (unsigned)(nb - 1));
    }
    __syncthreads();

    // ---- last block: final reduction (deterministic) ----
    if (is_last) {
        double s = 0.0;
        for (int j = threadIdx.x; j < nb; j += BLOCK)
            s += (double)g_partial[j];
#pragma unroll
        for (int o = 16; o > 0; o >>= 1)
            s += __shfl_down_sync(mask, s, o);
        __shared__ double ds[BLOCK / 32];
        if (lane == 0) ds[wid] = s;
        __syncthreads();
        if (threadIdx.x == 0) {
            double v = 0.0;
#pragma unroll
            for (int w = 0; w < BLOCK / 32; w++) v += ds[w];
            out[0] = (float)(v * (double)inv_n);
            g_count = 0;  // reset for next graph replay
        }
    }
}

extern "C" void kernel_launch(void* const* d_in, const int* in_sizes, int n_in,
                              void* d_out, int out_size) {
    const float* pred   = (const float*)d_in[0];
    const float* target = (const float*)d_in[1];
    const float* weight = (const float*)d_in[2];
    float* out = (float*)d_out;
    int n = in_sizes[2];

    int grid = (n + BLOCK - 1) / BLOCK;
    if (grid > MAXB) grid = MAXB;  // n = 1e6 -> 3907 blocks
    rl_main<<<grid, BLOCK>>>(pred, target, weight, out, n, grid,
                             1.0f / (float)n);
}

// round 8
// speedup vs baseline: 3.1774x; 1.0784x over previous
#include <cuda_runtime.h>
#include <math.h>

// ---------------------------------------------------------------------------
// RotatedIoULoss — separable Green's-theorem form.
//
// Box1 in box2's frame; box2 = [-hw,hw] x [-hh,hh].
// area(P ∩ box) = ∮_∂P clampx(x) d(clampy(y)).  Per edge (affine in t):
//   contribution = dy * ∫_{[a,b]} clampx(x(t)) dt,
//   [a,b] = [0,1] ∩ {t : |y(t)| <= hh}  (saturate of y-crossing params),
//   integrand piecewise-affine with breakpoints c1,c2 = x-crossing params
//   clamped to [a,b]  ->  3 trapezoids:
//   e = Xa(c1-a) + X1(c2-a) + X2(b-c1) + Xb(b-c2);  area += 0.5*dy*e.
// Opposite rectangle edges have negated directions -> 4 RCPs total.
// Degenerate edges (NaN/inf params) collapse to zero-width pieces or are
// killed by the dy=0 factor under CUDA fminf/fmaxf/__saturatef semantics.
// ---------------------------------------------------------------------------

#define IOU_EPS 1e-6f
#define BLOCK 256
#define MAXB  8192

__device__ float g_partial[MAXB];
__device__ unsigned int g_count = 0;   // reset by last block each launch

__device__ __forceinline__ float clampab(float v, float h) {
    return fminf(fmaxf(v, -h), h);
}

__global__ void __launch_bounds__(BLOCK, 6)
rl_main(const float* __restrict__ pred,
        const float* __restrict__ target,
        const float* __restrict__ weight,
        float* __restrict__ out,
        int n, int nb, float inv_n) {
    // ---- coalesced float4 staging of stride-5 rows ----
    __shared__ float4 sp4[BLOCK * 5 / 4];
    __shared__ float4 st4[BLOCK * 5 / 4];
    float* sp = (float*)sp4;
    float* st = (float*)st4;
    int bbase = blockIdx.x * BLOCK;
    int gbase = bbase * 5;
    int limit = n * 5 - gbase;
    const float4* p4 = (const float4*)(pred + gbase);
    const float4* t4 = (const float4*)(target + gbase);
    for (int j = threadIdx.x; j < BLOCK * 5 / 4; j += BLOCK) {
        float4 vp = make_float4(0.f, 0.f, 0.f, 0.f);
        float4 vt = vp;
        int e0 = j * 4;
        if (e0 + 3 < limit) {
            vp = p4[j]; vt = t4[j];
        } else if (e0 < limit) {
            const float* ps = pred + gbase;
            const float* ts = target + gbase;
            float* vpf = &vp.x; float* vtf = &vt.x;
            for (int c = 0; c < 4; c++)
                if (e0 + c < limit) { vpf[c] = ps[e0 + c]; vtf[c] = ts[e0 + c]; }
        }
        sp4[j] = vp; st4[j] = vt;
    }
    __syncthreads();

    int i = bbase + threadIdx.x;
    float loss = 0.f;
    if (i < n) {
        float w = weight[i];
        const float* P = sp + threadIdx.x * 5;
        const float* T = st + threadIdx.x * 5;
        float px = P[0], py = P[1], pw = P[2], ph = P[3], pa = P[4];
        float qx = T[0], qy = T[1], qw = T[2], qh = T[3], qa = T[4];

        // box1 in box2's local frame
        float cb, sb; __sincosf(qa, &sb, &cb);
        float dxc = px - qx, dyc = py - qy;
        float ox =  dxc * cb + dyc * sb;
        float oy = -dxc * sb + dyc * cb;
        float cr, sr; __sincosf(pa - qa, &sr, &cr);

        float hw = 0.5f * qw, hh = 0.5f * qh;
        float hx = 0.5f * pw, hy = 0.5f * ph;

        float ux = hx * cr,  uy = hx * sr;
        float wxr = -hy * sr, wyr = hy * cr;
        // corners (CCW): v0=(+u+w), v1=(-u+w), v2=(-u-w), v3=(+u-w)
        float v0x = ox + ux + wxr, v0y = oy + uy + wyr;
        float v1x = ox - ux + wxr, v1y = oy - uy + wyr;
        float v2x = ox - ux - wxr, v2y = oy - uy - wyr;
        float v3x = ox + ux - wxr, v3y = oy + uy - wyr;

        // edge directions: A = v3->v0 = (2wxr,2wyr), B = v0->v1 = (-2ux,-2uy)
        // C = v1->v2 = -A, D = v2->v3 = -B.  4 RCPs, negated reuse.
        float dAx = 2.f * wxr, dAy = 2.f * wyr;
        float dBx = -2.f * ux, dBy = -2.f * uy;
        float iAx = __fdividef(1.f, dAx), iAy = __fdividef(1.f, dAy);
        float iBx = __fdividef(1.f, dBx), iBy = __fdividef(1.f, dBy);
        float hwA = hw * iAx, hhA = hh * iAy;
        float hwB = hw * iBx, hhB = hh * iBy;

        float area2 = 0.f;   // accumulates Σ dy*e; area = 0.5*|area2|

        // edge from (axv,ayv), direction (dx_,dy_), reciprocals (ix_,iy_),
        // premultiplied slab/recip products (hwI,hhI)
#define EDGE(axv, ayv, dx_, dy_, ix_, iy_, hwI, hhI) do {              \
            float ta = fmaf((axv), -(ix_), -(hwI));                    \
            float tb = fmaf((axv), -(ix_),  (hwI));                    \
            float tc = fmaf((ayv), -(iy_), -(hhI));                    \
            float td = fmaf((ayv), -(iy_),  (hhI));                    \
            float a_ = __saturatef(fminf(tc, td));                     \
            float b_ = __saturatef(fmaxf(tc, td));                     \
            float t1 = fminf(ta, tb), t2 = fmaxf(ta, tb);              \
            float c1 = fminf(fmaxf(t1, a_), b_);                       \
            float c2 = fminf(fmaxf(t2, a_), b_);                       \
            float Xa = clampab(fmaf(a_, (dx_), (axv)), hw);            \
            float X1 = clampab(fmaf(c1, (dx_), (axv)), hw);            \
            float X2 = clampab(fmaf(c2, (dx_), (axv)), hw);            \
            float Xb = clampab(fmaf(b_, (dx_), (axv)), hw);            \
            float e = Xa * (c1 - a_);                                  \
            e = fmaf(X1, c2 - a_, e);                                  \
            e = fmaf(X2, b_ - c1, e);                                  \
            e = fmaf(Xb, b_ - c2, e);                                  \
            area2 = fmaf((dy_), e, area2);                             \
        } while (0)

        EDGE(v3x, v3y,  dAx,  dAy,  iAx,  iAy,  hwA,  hhA);  // v3->v0
        EDGE(v0x, v0y,  dBx,  dBy,  iBx,  iBy,  hwB,  hhB);  // v0->v1
        EDGE(v1x, v1y, -dAx, -dAy, -iAx, -iAy, -hwA, -hhA);  // v1->v2
        EDGE(v2x, v2y, -dBx, -dBy, -iBx, -iBy, -hwB, -hhB);  // v2->v3
#undef EDGE

        float inter = 0.5f * fabsf(area2);

        // conservative separation: certain-disjoint -> exact zero
        float rad = hx + hy;
        if (fabsf(ox) > hw + rad || fabsf(oy) > hh + rad) inter = 0.f;

        float a1 = pw * ph, a2 = qw * qh;
        float iou = __fdividef(inter, a1 + a2 - inter);
        iou = fmaxf(iou, IOU_EPS);
        loss = -__logf(iou) * w;
    }

    // ---- block reduction -> per-block partial ----
    unsigned mask = 0xFFFFFFFFu;
#pragma unroll
    for (int o = 16; o > 0; o >>= 1)
        loss += __shfl_down_sync(mask, loss, o);

    __shared__ float ws[BLOCK / 32];
    int lane = threadIdx.x & 31;
    int wid = threadIdx.x >> 5;
    if (lane == 0) ws[wid] = loss;
    __syncthreads();
    __shared__ bool is_last;
    if (threadIdx.x == 0) {
        float v = 0.f;
#pragma unroll
        for (int w = 0; w < BLOCK / 32; w++) v += ws[w];
        g_partial[blockIdx.x] = v;
        __threadfence();
        unsigned prev = atomicAdd(&g_count, 1u);
        is_last = (prev == (unsigned)(nb - 1));
    }
    __syncthreads();

    // ---- last block: final reduction (deterministic) ----
    if (is_last) {
        double s = 0.0;
        for (int j = threadIdx.x; j < nb; j += BLOCK)
            s += (double)g_partial[j];
#pragma unroll
        for (int o = 16; o > 0; o >>= 1)
            s += __shfl_down_sync(mask, s, o);
        __shared__ double ds[BLOCK / 32];
        if (lane == 0) ds[wid] = s;
        __syncthreads();
        if (threadIdx.x == 0) {
            double v = 0.0;
#pragma unroll
            for (int w = 0; w < BLOCK / 32; w++) v += ds[w];
            out[0] = (float)(v * (double)inv_n);
            g_count = 0;  // reset for next graph replay
        }
    }
}

extern "C" void kernel_launch(void* const* d_in, const int* in_sizes, int n_in,
                              void* d_out, int out_size) {
    const float* pred   = (const float*)d_in[0];
    const float* target = (const float*)d_in[1];
    const float* weight = (const float*)d_in[2];
    float* out = (float*)d_out;
    int n = in_sizes[2];

    int grid = (n + BLOCK - 1) / BLOCK;
    if (grid > MAXB) grid = MAXB;  // n = 1e6 -> 3907 blocks
    rl_main<<<grid, BLOCK>>>(pred, target, weight, out, n, grid,
                             1.0f / (float)n);
}

// round 9
// speedup vs baseline: 3.8436x; 1.2097x over previous
#include <cuda_runtime.h>
#include <math.h>

// ---------------------------------------------------------------------------
// RotatedIoULoss — separable Green's-theorem form, 2 boxes per thread.
//
// Box1 in box2's frame; box2 = [-hw,hw] x [-hh,hh].
// area(P ∩ box) = ∮_∂P clampx(x) d(clampy(y)).  Per edge (affine in t):
//   contribution = dy * ∫_{[a,b]} clampx(x(t)) dt,
//   [a,b] = [0,1] ∩ y-slab interval, breakpoints c1,c2 = x-crossing params
//   clamped to [a,b] -> 3 trapezoids. 4 RCPs per box (opposite edges reuse
//   negated reciprocals). NaN/inf degenerate params collapse to zero-width
//   pieces or are killed by the dy factor (CUDA fmin/fmax/saturate NaN rules).
//
// Two boxes per thread: two independent dependency chains interleave to hide
// MUFU/FMA latency; per-block fixed costs amortize over 2x boxes.
// ---------------------------------------------------------------------------

#define IOU_EPS 1e-6f
#define BLOCK 256
#define PERB  (2 * BLOCK)          // boxes per block
#define MAXB  8192

__device__ float g_partial[MAXB];
__device__ unsigned int g_count = 0;   // reset by last block each launch

__device__ __forceinline__ float clampab(float v, float h) {
    return fminf(fmaxf(v, -h), h);
}

__device__ __forceinline__ float box_loss(const float* __restrict__ P,
                                          const float* __restrict__ T,
                                          float w) {
    float px = P[0], py = P[1], pw = P[2], ph = P[3], pa = P[4];
    float qx = T[0], qy = T[1], qw = T[2], qh = T[3], qa = T[4];

    // box1 in box2's local frame
    float cb, sb; __sincosf(qa, &sb, &cb);
    float dxc = px - qx, dyc = py - qy;
    float ox =  dxc * cb + dyc * sb;
    float oy = -dxc * sb + dyc * cb;
    float cr, sr; __sincosf(pa - qa, &sr, &cr);

    float hw = 0.5f * qw, hh = 0.5f * qh;
    float hx = 0.5f * pw, hy = 0.5f * ph;

    float ux = hx * cr,  uy = hx * sr;
    float wxr = -hy * sr, wyr = hy * cr;
    float v0x = ox + ux + wxr, v0y = oy + uy + wyr;
    float v1x = ox - ux + wxr, v1y = oy - uy + wyr;
    float v2x = ox - ux - wxr, v2y = oy - uy - wyr;
    float v3x = ox + ux - wxr, v3y = oy + uy - wyr;

    float dAx = 2.f * wxr, dAy = 2.f * wyr;
    float dBx = -2.f * ux, dBy = -2.f * uy;
    float iAx = __fdividef(1.f, dAx), iAy = __fdividef(1.f, dAy);
    float iBx = __fdividef(1.f, dBx), iBy = __fdividef(1.f, dBy);
    float hwA = hw * iAx, hhA = hh * iAy;
    float hwB = hw * iBx, hhB = hh * iBy;

    float area2 = 0.f;

#define EDGE(axv, ayv, dx_, dy_, ix_, iy_, hwI, hhI) do {              \
        float ta = fmaf((axv), -(ix_), -(hwI));                        \
        float tb = fmaf((axv), -(ix_),  (hwI));                        \
        float tc = fmaf((ayv), -(iy_), -(hhI));                        \
        float td = fmaf((ayv), -(iy_),  (hhI));                        \
        float a_ = __saturatef(fminf(tc, td));                         \
        float b_ = __saturatef(fmaxf(tc, td));                         \
        float t1 = fminf(ta, tb), t2 = fmaxf(ta, tb);                  \
        float c1 = fminf(fmaxf(t1, a_), b_);                           \
        float c2 = fminf(fmaxf(t2, a_), b_);                           \
        float Xa = clampab(fmaf(a_, (dx_), (axv)), hw);                \
        float X1 = clampab(fmaf(c1, (dx_), (axv)), hw);                \
        float X2 = clampab(fmaf(c2, (dx_), (axv)), hw);                \
        float Xb = clampab(fmaf(b_, (dx_), (axv)), hw);                \
        float e = Xa * (c1 - a_);                                      \
        e = fmaf(X1, c2 - a_, e);                                      \
        e = fmaf(X2, b_ - c1, e);                                      \
        e = fmaf(Xb, b_ - c2, e);                                      \
        area2 = fmaf((dy_), e, area2);                                 \
    } while (0)

    EDGE(v3x, v3y,  dAx,  dAy,  iAx,  iAy,  hwA,  hhA);
    EDGE(v0x, v0y,  dBx,  dBy,  iBx,  iBy,  hwB,  hhB);
    EDGE(v1x, v1y, -dAx, -dAy, -iAx, -iAy, -hwA, -hhA);
    EDGE(v2x, v2y, -dBx, -dBy, -iBx, -iBy, -hwB, -hhB);
#undef EDGE

    float inter = 0.5f * fabsf(area2);

    // conservative separation: certain-disjoint -> exact zero (predicated)
    float rad = hx + hy;
    bool sep = (fabsf(ox) > hw + rad) || (fabsf(oy) > hh + rad);
    inter = sep ? 0.f : inter;

    float a1 = pw * ph, a2 = qw * qh;
    float iou = __fdividef(inter, a1 + a2 - inter);
    iou = fmaxf(iou, IOU_EPS);
    return -__logf(iou) * w;
}

__global__ void __launch_bounds__(BLOCK, 4)
rl_main(const float* __restrict__ pred,
        const float* __restrict__ target,
        const float* __restrict__ weight,
        float* __restrict__ out,
        int n, int nb, float inv_n) {
    // ---- coalesced float4 staging of stride-5 rows (PERB boxes) ----
    __shared__ float4 sp4[PERB * 5 / 4];
    __shared__ float4 st4[PERB * 5 / 4];
    float* sp = (float*)sp4;
    float* st = (float*)st4;
    int bbase = blockIdx.x * PERB;
    int gbase = bbase * 5;
    int limit = n * 5 - gbase;
    const float4* p4 = (const float4*)(pred + gbase);
    const float4* t4 = (const float4*)(target + gbase);
#pragma unroll
    for (int j = threadIdx.x; j < PERB * 5 / 4; j += BLOCK) {
        float4 vp = make_float4(0.f, 0.f, 0.f, 0.f);
        float4 vt = vp;
        int e0 = j * 4;
        if (e0 + 3 < limit) {
            vp = p4[j]; vt = t4[j];
        } else if (e0 < limit) {
            const float* ps = pred + gbase;
            const float* ts = target + gbase;
            float* vpf = &vp.x; float* vtf = &vt.x;
            for (int c = 0; c < 4; c++)
                if (e0 + c < limit) { vpf[c] = ps[e0 + c]; vtf[c] = ts[e0 + c]; }
        }
        sp4[j] = vp; st4[j] = vt;
    }
    __syncthreads();

    int i0 = bbase + threadIdx.x;
    int i1 = i0 + BLOCK;
    float loss = 0.f;
    if (i0 < n) {
        float w0 = weight[i0];
        loss = box_loss(sp + threadIdx.x * 5, st + threadIdx.x * 5, w0);
    }
    if (i1 < n) {
        float w1 = weight[i1];
        loss += box_loss(sp + (threadIdx.x + BLOCK) * 5,
                         st + (threadIdx.x + BLOCK) * 5, w1);
    }

    // ---- block reduction -> per-block partial ----
    unsigned mask = 0xFFFFFFFFu;
#pragma unroll
    for (int o = 16; o > 0; o >>= 1)
        loss += __shfl_down_sync(mask, loss, o);

    __shared__ float ws[BLOCK / 32];
    int lane = threadIdx.x & 31;
    int wid = threadIdx.x >> 5;
    if (lane == 0) ws[wid] = loss;
    __syncthreads();
    __shared__ bool is_last;
    if (threadIdx.x == 0) {
        float v = 0.f;
#pragma unroll
        for (int w = 0; w < BLOCK / 32; w++) v += ws[w];
        g_partial[blockIdx.x] = v;
        __threadfence();
        unsigned prev = atomicAdd(&g_count, 1u);
        is_last = (prev == (unsigned)(nb - 1));
    }
    __syncthreads();

    // ---- last block: final reduction (deterministic) ----
    if (is_last) {
        double s = 0.0;
        for (int j = threadIdx.x; j < nb; j += BLOCK)
            s += (double)g_partial[j];
#pragma unroll
        for (int o = 16; o > 0; o >>= 1)
            s += __shfl_down_sync(mask, s, o);
        __shared__ double ds[BLOCK / 32];
        if (lane == 0) ds[wid] = s;
        __syncthreads();
        if (threadIdx.x == 0) {
            double v = 0.0;
#pragma unroll
            for (int w = 0; w < BLOCK / 32; w++) v += ds[w];
            out[0] = (float)(v * (double)inv_n);
            g_count = 0;  // reset for next graph replay
        }
    }
}

extern "C" void kernel_launch(void* const* d_in, const int* in_sizes, int n_in,
                              void* d_out, int out_size) {
    const float* pred   = (const float*)d_in[0];
    const float* target = (const float*)d_in[1];
    const float* weight = (const float*)d_in[2];
    float* out = (float*)d_out;
    int n = in_sizes[2];

    int grid = (n + PERB - 1) / PERB;
    if (grid > MAXB) grid = MAXB;  // n = 1e6 -> 1954 blocks
    rl_main<<<grid, BLOCK>>>(pred, target, weight, out, n, grid,
                             1.0f / (float)n);
}

// round 10
// speedup vs baseline: 3.9020x; 1.0152x over previous
#include <cuda_runtime.h>
#include <math.h>

// ---------------------------------------------------------------------------
// RotatedIoULoss — separable Green's-theorem form in the unit box,
// 2 boxes per thread.
//
// Coordinates scaled by (1/hw, 1/hh) so box2 = [-1,1]^2 (clamp limits are
// immediates). area(P ∩ box2) = hw*hh * ∮ clampx(X) d(clampy(Y)) over the
// scaled boundary. Per edge: y-slab window [a,b] (saturated crossing params),
// x-crossing breakpoints clamped into [a,b], 3 trapezoids:
//   e = Xa(c1-a) + X1(c2-a) + X2(b-c1) + Xb(b-c2);  area2 += dy*e.
// Edge reciprocals stay independent (axis-parallel edges resolve through
// +/-inf under fmin/fmax/saturate semantics); 1/hw,1/hh share one RCP.
// ---------------------------------------------------------------------------

#define IOU_EPS 1e-6f
#define BLOCK 256
#define PERB  (2 * BLOCK)          // boxes per block
#define MAXB  8192

__device__ float g_partial[MAXB];
__device__ unsigned int g_count = 0;   // reset by last block each launch

__device__ __forceinline__ float clamp1(float v) {
    return fminf(fmaxf(v, -1.f), 1.f);
}

__device__ __forceinline__ float box_loss(const float* __restrict__ P,
                                          const float* __restrict__ T,
                                          float w) {
    float px = P[0], py = P[1], pw = P[2], ph = P[3], pa = P[4];
    float qx = T[0], qy = T[1], qw = T[2], qh = T[3], qa = T[4];

    // frame change into box2's local axes
    float cb, sb; __sincosf(qa, &sb, &cb);
    float dxc = px - qx, dyc = py - qy;
    float ox =  dxc * cb + dyc * sb;
    float oy = -dxc * sb + dyc * cb;
    float cr, sr; __sincosf(pa - qa, &sr, &cr);

    float hw = 0.5f * qw, hh = 0.5f * qh;
    float hx = 0.5f * pw, hy = 0.5f * ph;

    // unit-box scaling: one RCP serves both axes (hw,hh >= 0.5 in data)
    float hwh  = hw * hh;
    float ihwh = __fdividef(1.f, hwh);
    float ihw = hh * ihwh, ihh = hw * ihwh;

    float Ox = ox * ihw, Oy = oy * ihh;
    float Ux = (hx * cr) * ihw, Uy = (hx * sr) * ihh;
    float Wx = -(hy * sr) * ihw, Wy = (hy * cr) * ihh;

    // scaled corners (CCW)
    float v0x = Ox + Ux + Wx, v0y = Oy + Uy + Wy;
    float v1x = Ox - Ux + Wx, v1y = Oy - Uy + Wy;
    float v2x = Ox - Ux - Wx, v2y = Oy - Uy - Wy;
    float v3x = Ox + Ux - Wx, v3y = Oy + Uy - Wy;

    // edge dirs: A = v3->v0 = 2W, B = v0->v1 = -2U (C=-A, D=-B)
    float dAx = 2.f * Wx, dAy = 2.f * Wy;
    float dBx = -2.f * Ux, dBy = -2.f * Uy;
    float iAx = __fdividef(1.f, dAx), iAy = __fdividef(1.f, dAy);
    float iBx = __fdividef(1.f, dBx), iBy = __fdividef(1.f, dBy);

    float area2 = 0.f;

#define EDGE(axv, ayv, dx_, dy_, ix_, iy_) do {                        \
        float ta = fmaf((axv), -(ix_), -(ix_));   /* (-1-ax)*ix */     \
        float tb = fmaf((axv), -(ix_),  (ix_));   /* ( 1-ax)*ix */     \
        float tc = fmaf((ayv), -(iy_), -(iy_));                        \
        float td = fmaf((ayv), -(iy_),  (iy_));                        \
        float a_ = __saturatef(fminf(tc, td));                         \
        float b_ = __saturatef(fmaxf(tc, td));                         \
        float t1 = fminf(ta, tb), t2 = fmaxf(ta, tb);                  \
        float c1 = fminf(fmaxf(t1, a_), b_);                           \
        float c2 = fminf(fmaxf(t2, a_), b_);                           \
        float Xa = clamp1(fmaf(a_, (dx_), (axv)));                     \
        float X1 = clamp1(fmaf(c1, (dx_), (axv)));                     \
        float X2 = clamp1(fmaf(c2, (dx_), (axv)));                     \
        float Xb = clamp1(fmaf(b_, (dx_), (axv)));                     \
        float e = Xa * (c1 - a_);                                      \
        e = fmaf(X1, c2 - a_, e);                                      \
        e = fmaf(X2, b_ - c1, e);                                      \
        e = fmaf(Xb, b_ - c2, e);                                      \
        area2 = fmaf((dy_), e, area2);                                 \
    } while (0)

    EDGE(v3x, v3y,  dAx,  dAy,  iAx,  iAy);
    EDGE(v0x, v0y,  dBx,  dBy,  iBx,  iBy);
    EDGE(v1x, v1y, -dAx, -dAy, -iAx, -iAy);
    EDGE(v2x, v2y, -dBx, -dBy, -iBx, -iBy);
#undef EDGE

    float inter = 0.5f * fabsf(area2) * hwh;

    // conservative separation: certain-disjoint -> exact zero (predicated)
    float radx = fabsf(Ux) + fabsf(Wx);
    float rady = fabsf(Uy) + fabsf(Wy);
    bool sep = (fabsf(Ox) > 1.f + radx) || (fabsf(Oy) > 1.f + rady);
    inter = sep ? 0.f : inter;

    float a1 = pw * ph, a2 = qw * qh;
    float iou = __fdividef(inter, a1 + a2 - inter);
    iou = fmaxf(iou, IOU_EPS);
    return -__logf(iou) * w;
}

__global__ void __launch_bounds__(BLOCK, 5)
rl_main(const float* __restrict__ pred,
        const float* __restrict__ target,
        const float* __restrict__ weight,
        float* __restrict__ out,
        int n, int nb, float inv_n) {
    // ---- coalesced float4 staging of stride-5 rows (PERB boxes) ----
    __shared__ float4 sp4[PERB * 5 / 4];
    __shared__ float4 st4[PERB * 5 / 4];
    float* sp = (float*)sp4;
    float* st = (float*)st4;
    int bbase = blockIdx.x * PERB;
    int gbase = bbase * 5;
    int limit = n * 5 - gbase;
    const float4* p4 = (const float4*)(pred + gbase);
    const float4* t4 = (const float4*)(target + gbase);
    if (limit >= PERB * 5) {
        // fast path: full block, no bounds checks
#pragma unroll
        for (int j = threadIdx.x; j < PERB * 5 / 4; j += BLOCK) {
            sp4[j] = p4[j];
            st4[j] = t4[j];
        }
    } else {
        for (int j = threadIdx.x; j < PERB * 5 / 4; j += BLOCK) {
            float4 vp = make_float4(0.f, 0.f, 0.f, 0.f);
            float4 vt = vp;
            int e0 = j * 4;
            if (e0 + 3 < limit) {
                vp = p4[j]; vt = t4[j];
            } else if (e0 < limit) {
                const float* ps = pred + gbase;
                const float* ts = target + gbase;
                float* vpf = &vp.x; float* vtf = &vt.x;
                for (int c = 0; c < 4; c++)
                    if (e0 + c < limit) { vpf[c] = ps[e0 + c]; vtf[c] = ts[e0 + c]; }
            }
            sp4[j] = vp; st4[j] = vt;
        }
    }
    __syncthreads();

    int i0 = bbase + threadIdx.x;
    int i1 = i0 + BLOCK;
    float loss = 0.f;
    if (i0 < n) {
        float w0 = weight[i0];
        loss = box_loss(sp + threadIdx.x * 5, st + threadIdx.x * 5, w0);
    }
    if (i1 < n) {
        float w1 = weight[i1];
        loss += box_loss(sp + (threadIdx.x + BLOCK) * 5,
                         st + (threadIdx.x + BLOCK) * 5, w1);
    }

    // ---- block reduction -> per-block partial ----
    unsigned mask = 0xFFFFFFFFu;
#pragma unroll
    for (int o = 16; o > 0; o >>= 1)
        loss += __shfl_down_sync(mask, loss, o);

    __shared__ float ws[BLOCK / 32];
    int lane = threadIdx.x & 31;
    int wid = threadIdx.x >> 5;
    if (lane == 0) ws[wid] = loss;
    __syncthreads();
    __shared__ bool is_last;
    if (threadIdx.x == 0) {
        float v = 0.f;
#pragma unroll
        for (int w = 0; w < BLOCK / 32; w++) v += ws[w];
        g_partial[blockIdx.x] = v;
        __threadfence();
        unsigned prev = atomicAdd(&g_count, 1u);
        is_last = (prev == (unsigned)(nb - 1));
    }
    __syncthreads();

    // ---- last block: final reduction (deterministic) ----
    if (is_last) {
        double s = 0.0;
        for (int j = threadIdx.x; j < nb; j += BLOCK)
            s += (double)g_partial[j];
#pragma unroll
        for (int o = 16; o > 0; o >>= 1)
            s += __shfl_down_sync(mask, s, o);
        __shared__ double ds[BLOCK / 32];
        if (lane == 0) ds[wid] = s;
        __syncthreads();
        if (threadIdx.x == 0) {
            double v = 0.0;
#pragma unroll
            for (int w = 0; w < BLOCK / 32; w++) v += ds[w];
            out[0] = (float)(v * (double)inv_n);
            g_count = 0;  // reset for next graph replay
        }
    }
}

extern "C" void kernel_launch(void* const* d_in, const int* in_sizes, int n_in,
                              void* d_out, int out_size) {
    const float* pred   = (const float*)d_in[0];
    const float* target = (const float*)d_in[1];
    const float* weight = (const float*)d_in[2];
    float* out = (float*)d_out;
    int n = in_sizes[2];

    int grid = (n + PERB - 1) / PERB;
    if (grid > MAXB) grid = MAXB;  // n = 1e6 -> 1954 blocks
    rl_main<<<grid, BLOCK>>>(pred, target, weight, out, n, grid,
                             1.0f / (float)n);
}